// round 14
// baseline (speedup 1.0000x reference)
#include <cuda_runtime.h>

// GNN_70145405878616 — FINAL (best measured 111.5us ≈ 7.1 TB/s effective):
// 8 lanes/node, coalesced 128B streaming loads (__ldcs), 3-lane epilogue,
// smem-staged sector-exact float4 output stores, 256-thread blocks.
// out[b,o] = tanh(tanh( bc[o] + sum_c Wc[o,c,0]*h[b,c] + Wc[o,c,1]*p[b,c] ))
//   h[b,c] = tanh( bs[c] + sum_j Ws[c,j]*x[b,j] ),  p[b,c] = mean_k nb[b,c,k]

__device__ __forceinline__ float htanh(float x) {
    float y;
    asm("tanh.approx.f32 %0, %1;" : "=f"(y) : "f"(x));
    return y;
}

__global__ __launch_bounds__(256) void gnn_kernel(
        const float* __restrict__ x,
        const float* __restrict__ nb,
        const float* __restrict__ Ws,
        const float* __restrict__ bs,
        const float* __restrict__ Wc,
        const float* __restrict__ bc,
        float* __restrict__ out,
        int B) {
    __shared__ float so[96];               // 32 nodes * 3 channels = 384 B

    const int gtid  = blockIdx.x * blockDim.x + threadIdx.x;
    const int node  = gtid >> 3;           // 8 lanes per node
    const int lane  = gtid & 7;
    const int lnode = threadIdx.x >> 3;    // node index within block (0..31)
    const bool live = (node < B);

    float s0 = 0.f, s1 = 0.f, s2 = 0.f;
    float x0 = 0.f, x1 = 0.f, x2 = 0.f;

    if (live) {
        const float4* __restrict__ base =
            reinterpret_cast<const float4*>(nb) + (size_t)node * 48;

        // Channel c occupies float4s [c*16, c*16+16). Lane l takes l and l+8.
        // Evict-first: stream is read exactly once.
        float4 a0 = __ldcs(base + lane),      b0 = __ldcs(base + lane + 8);
        float4 a1 = __ldcs(base + lane + 16), b1 = __ldcs(base + lane + 24);
        float4 a2 = __ldcs(base + lane + 32), b2 = __ldcs(base + lane + 40);

        if (lane < 3) {
            const float* __restrict__ xp = x + (size_t)node * 3;
            x0 = __ldg(xp + 0); x1 = __ldg(xp + 1); x2 = __ldg(xp + 2);
        }

        s0 = ((a0.x + b0.x) + (a0.y + b0.y)) + ((a0.z + b0.z) + (a0.w + b0.w));
        s1 = ((a1.x + b1.x) + (a1.y + b1.y)) + ((a1.z + b1.z) + (a1.w + b1.w));
        s2 = ((a2.x + b2.x) + (a2.y + b2.y)) + ((a2.z + b2.z) + (a2.w + b2.w));
    }

    // Reduce across the 8-lane group; all lanes end with the full sums.
    const unsigned gm = 0xFFu << (threadIdx.x & 24);
    #pragma unroll
    for (int off = 4; off > 0; off >>= 1) {
        s0 += __shfl_xor_sync(gm, s0, off);
        s1 += __shfl_xor_sync(gm, s1, off);
        s2 += __shfl_xor_sync(gm, s2, off);
    }

    if (live && lane < 3) {
        const int o = lane;
        const float inv = 1.0f / 64.0f;
        const float p[3] = { s0 * inv, s1 * inv, s2 * inv };

        float h[3];
        #pragma unroll
        for (int c = 0; c < 3; ++c) {
            h[c] = htanh(fmaf(__ldg(Ws + c * 3 + 0), x0,
                         fmaf(__ldg(Ws + c * 3 + 1), x1,
                         fmaf(__ldg(Ws + c * 3 + 2), x2, __ldg(bs + c)))));
        }

        float z = __ldg(bc + o);
        #pragma unroll
        for (int c = 0; c < 3; ++c) {
            z = fmaf(__ldg(Wc + o * 6 + c * 2 + 0), h[c], z);
            z = fmaf(__ldg(Wc + o * 6 + c * 2 + 1), p[c], z);
        }
        so[lnode * 3 + o] = htanh(htanh(z));
    }

    __syncthreads();

    // Sector-exact output: this block owns out[first*3 .. first*3+96),
    // a 384B 128-aligned span -> 24 float4 stores (full blocks only).
    const int first = blockIdx.x << 5;               // first node of block
    const int nodes_here = min(32, B - first);
    if (nodes_here == 32) {
        if (threadIdx.x < 24) {
            float4* __restrict__ o4 =
                reinterpret_cast<float4*>(out + (size_t)first * 3);
            const float4* s4 = reinterpret_cast<const float4*>(so);
            __stcs(o4 + threadIdx.x, s4[threadIdx.x]);
        }
    } else if (nodes_here > 0) {
        for (int i = threadIdx.x; i < nodes_here * 3; i += blockDim.x)
            out[(size_t)first * 3 + i] = so[i];
    }
}

extern "C" void kernel_launch(void* const* d_in, const int* in_sizes, int n_in,
                              void* d_out, int out_size) {
    const float* x  = (const float*)d_in[0];   // [B,3,1]
    const float* nb = (const float*)d_in[1];   // [B,3,64]
    const float* Ws = (const float*)d_in[2];   // [3,3]
    const float* bs = (const float*)d_in[3];   // [3]
    const float* Wc = (const float*)d_in[4];   // [3,3,2]
    const float* bc = (const float*)d_in[5];   // [3]
    float* out = (float*)d_out;                // [B,3,1]

    const int B = in_sizes[0] / 3;
    const int threads = 256;                   // 32 nodes per block
    const long long total = (long long)B * 8;
    const int blocks = (int)((total + threads - 1) / threads);

    gnn_kernel<<<blocks, threads>>>(x, nb, Ws, bs, Wc, bc, out, B);
}

// round 15
// speedup vs baseline: 1.1080x; 1.1080x over previous
#include <cuda_runtime.h>

// GNN_70145405878616 — FINAL (best measured 111.5us ≈ 7.1 TB/s effective):
// 8 lanes/node, coalesced 128B streaming loads (__ldcs), 3-lane epilogue,
// smem-staged sector-exact float4 output stores, 256-thread blocks.
// out[b,o] = tanh(tanh( bc[o] + sum_c Wc[o,c,0]*h[b,c] + Wc[o,c,1]*p[b,c] ))
//   h[b,c] = tanh( bs[c] + sum_j Ws[c,j]*x[b,j] ),  p[b,c] = mean_k nb[b,c,k]

__device__ __forceinline__ float htanh(float x) {
    float y;
    asm("tanh.approx.f32 %0, %1;" : "=f"(y) : "f"(x));
    return y;
}

__global__ __launch_bounds__(256) void gnn_kernel(
        const float* __restrict__ x,
        const float* __restrict__ nb,
        const float* __restrict__ Ws,
        const float* __restrict__ bs,
        const float* __restrict__ Wc,
        const float* __restrict__ bc,
        float* __restrict__ out,
        int B) {
    __shared__ float so[96];               // 32 nodes * 3 channels = 384 B

    const int gtid  = blockIdx.x * blockDim.x + threadIdx.x;
    const int node  = gtid >> 3;           // 8 lanes per node
    const int lane  = gtid & 7;
    const int lnode = threadIdx.x >> 3;    // node index within block (0..31)
    const bool live = (node < B);

    float s0 = 0.f, s1 = 0.f, s2 = 0.f;
    float x0 = 0.f, x1 = 0.f, x2 = 0.f;

    if (live) {
        const float4* __restrict__ base =
            reinterpret_cast<const float4*>(nb) + (size_t)node * 48;

        // Channel c occupies float4s [c*16, c*16+16). Lane l takes l and l+8.
        // Evict-first: stream is read exactly once.
        float4 a0 = __ldcs(base + lane),      b0 = __ldcs(base + lane + 8);
        float4 a1 = __ldcs(base + lane + 16), b1 = __ldcs(base + lane + 24);
        float4 a2 = __ldcs(base + lane + 32), b2 = __ldcs(base + lane + 40);

        if (lane < 3) {
            const float* __restrict__ xp = x + (size_t)node * 3;
            x0 = __ldg(xp + 0); x1 = __ldg(xp + 1); x2 = __ldg(xp + 2);
        }

        s0 = ((a0.x + b0.x) + (a0.y + b0.y)) + ((a0.z + b0.z) + (a0.w + b0.w));
        s1 = ((a1.x + b1.x) + (a1.y + b1.y)) + ((a1.z + b1.z) + (a1.w + b1.w));
        s2 = ((a2.x + b2.x) + (a2.y + b2.y)) + ((a2.z + b2.z) + (a2.w + b2.w));
    }

    // Reduce across the 8-lane group; all lanes end with the full sums.
    const unsigned gm = 0xFFu << (threadIdx.x & 24);
    #pragma unroll
    for (int off = 4; off > 0; off >>= 1) {
        s0 += __shfl_xor_sync(gm, s0, off);
        s1 += __shfl_xor_sync(gm, s1, off);
        s2 += __shfl_xor_sync(gm, s2, off);
    }

    if (live && lane < 3) {
        const int o = lane;
        const float inv = 1.0f / 64.0f;
        const float p[3] = { s0 * inv, s1 * inv, s2 * inv };

        float h[3];
        #pragma unroll
        for (int c = 0; c < 3; ++c) {
            h[c] = htanh(fmaf(__ldg(Ws + c * 3 + 0), x0,
                         fmaf(__ldg(Ws + c * 3 + 1), x1,
                         fmaf(__ldg(Ws + c * 3 + 2), x2, __ldg(bs + c)))));
        }

        float z = __ldg(bc + o);
        #pragma unroll
        for (int c = 0; c < 3; ++c) {
            z = fmaf(__ldg(Wc + o * 6 + c * 2 + 0), h[c], z);
            z = fmaf(__ldg(Wc + o * 6 + c * 2 + 1), p[c], z);
        }
        so[lnode * 3 + o] = htanh(htanh(z));
    }

    __syncthreads();

    // Sector-exact output: this block owns out[first*3 .. first*3+96),
    // a 384B 128-aligned span -> 24 float4 stores (full blocks only).
    const int first = blockIdx.x << 5;               // first node of block
    const int nodes_here = min(32, B - first);
    if (nodes_here == 32) {
        if (threadIdx.x < 24) {
            float4* __restrict__ o4 =
                reinterpret_cast<float4*>(out + (size_t)first * 3);
            const float4* s4 = reinterpret_cast<const float4*>(so);
            __stcs(o4 + threadIdx.x, s4[threadIdx.x]);
        }
    } else if (nodes_here > 0) {
        for (int i = threadIdx.x; i < nodes_here * 3; i += blockDim.x)
            out[(size_t)first * 3 + i] = so[i];
    }
}

extern "C" void kernel_launch(void* const* d_in, const int* in_sizes, int n_in,
                              void* d_out, int out_size) {
    const float* x  = (const float*)d_in[0];   // [B,3,1]
    const float* nb = (const float*)d_in[1];   // [B,3,64]
    const float* Ws = (const float*)d_in[2];   // [3,3]
    const float* bs = (const float*)d_in[3];   // [3]
    const float* Wc = (const float*)d_in[4];   // [3,3,2]
    const float* bc = (const float*)d_in[5];   // [3]
    float* out = (float*)d_out;                // [B,3,1]

    const int B = in_sizes[0] / 3;
    const int threads = 256;                   // 32 nodes per block
    const long long total = (long long)B * 8;
    const int blocks = (int)((total + threads - 1) / threads);

    gnn_kernel<<<blocks, threads>>>(x, nb, Ws, bs, Wc, bc, out, B);
}

// round 16
// speedup vs baseline: 1.1093x; 1.0012x over previous
#include <cuda_runtime.h>

// GNN_70145405878616 — FINAL (best measured 111.4us ≈ 7.1 TB/s effective):
// 8 lanes/node, coalesced 128B streaming loads (__ldcs), 3-lane epilogue,
// smem-staged sector-exact float4 output stores, 256-thread blocks.
// out[b,o] = tanh(tanh( bc[o] + sum_c Wc[o,c,0]*h[b,c] + Wc[o,c,1]*p[b,c] ))
//   h[b,c] = tanh( bs[c] + sum_j Ws[c,j]*x[b,j] ),  p[b,c] = mean_k nb[b,c,k]

__device__ __forceinline__ float htanh(float x) {
    float y;
    asm("tanh.approx.f32 %0, %1;" : "=f"(y) : "f"(x));
    return y;
}

__global__ __launch_bounds__(256) void gnn_kernel(
        const float* __restrict__ x,
        const float* __restrict__ nb,
        const float* __restrict__ Ws,
        const float* __restrict__ bs,
        const float* __restrict__ Wc,
        const float* __restrict__ bc,
        float* __restrict__ out,
        int B) {
    __shared__ float so[96];               // 32 nodes * 3 channels = 384 B

    const int gtid  = blockIdx.x * blockDim.x + threadIdx.x;
    const int node  = gtid >> 3;           // 8 lanes per node
    const int lane  = gtid & 7;
    const int lnode = threadIdx.x >> 3;    // node index within block (0..31)
    const bool live = (node < B);

    float s0 = 0.f, s1 = 0.f, s2 = 0.f;
    float x0 = 0.f, x1 = 0.f, x2 = 0.f;

    if (live) {
        const float4* __restrict__ base =
            reinterpret_cast<const float4*>(nb) + (size_t)node * 48;

        // Channel c occupies float4s [c*16, c*16+16). Lane l takes l and l+8.
        // Evict-first: stream is read exactly once.
        float4 a0 = __ldcs(base + lane),      b0 = __ldcs(base + lane + 8);
        float4 a1 = __ldcs(base + lane + 16), b1 = __ldcs(base + lane + 24);
        float4 a2 = __ldcs(base + lane + 32), b2 = __ldcs(base + lane + 40);

        if (lane < 3) {
            const float* __restrict__ xp = x + (size_t)node * 3;
            x0 = __ldg(xp + 0); x1 = __ldg(xp + 1); x2 = __ldg(xp + 2);
        }

        s0 = ((a0.x + b0.x) + (a0.y + b0.y)) + ((a0.z + b0.z) + (a0.w + b0.w));
        s1 = ((a1.x + b1.x) + (a1.y + b1.y)) + ((a1.z + b1.z) + (a1.w + b1.w));
        s2 = ((a2.x + b2.x) + (a2.y + b2.y)) + ((a2.z + b2.z) + (a2.w + b2.w));
    }

    // Reduce across the 8-lane group; all lanes end with the full sums.
    const unsigned gm = 0xFFu << (threadIdx.x & 24);
    #pragma unroll
    for (int off = 4; off > 0; off >>= 1) {
        s0 += __shfl_xor_sync(gm, s0, off);
        s1 += __shfl_xor_sync(gm, s1, off);
        s2 += __shfl_xor_sync(gm, s2, off);
    }

    if (live && lane < 3) {
        const int o = lane;
        const float inv = 1.0f / 64.0f;
        const float p[3] = { s0 * inv, s1 * inv, s2 * inv };

        float h[3];
        #pragma unroll
        for (int c = 0; c < 3; ++c) {
            h[c] = htanh(fmaf(__ldg(Ws + c * 3 + 0), x0,
                         fmaf(__ldg(Ws + c * 3 + 1), x1,
                         fmaf(__ldg(Ws + c * 3 + 2), x2, __ldg(bs + c)))));
        }

        float z = __ldg(bc + o);
        #pragma unroll
        for (int c = 0; c < 3; ++c) {
            z = fmaf(__ldg(Wc + o * 6 + c * 2 + 0), h[c], z);
            z = fmaf(__ldg(Wc + o * 6 + c * 2 + 1), p[c], z);
        }
        so[lnode * 3 + o] = htanh(htanh(z));
    }

    __syncthreads();

    // Sector-exact output: this block owns out[first*3 .. first*3+96),
    // a 384B 128-aligned span -> 24 float4 stores (full blocks only).
    const int first = blockIdx.x << 5;               // first node of block
    const int nodes_here = min(32, B - first);
    if (nodes_here == 32) {
        if (threadIdx.x < 24) {
            float4* __restrict__ o4 =
                reinterpret_cast<float4*>(out + (size_t)first * 3);
            const float4* s4 = reinterpret_cast<const float4*>(so);
            __stcs(o4 + threadIdx.x, s4[threadIdx.x]);
        }
    } else if (nodes_here > 0) {
        for (int i = threadIdx.x; i < nodes_here * 3; i += blockDim.x)
            out[(size_t)first * 3 + i] = so[i];
    }
}

extern "C" void kernel_launch(void* const* d_in, const int* in_sizes, int n_in,
                              void* d_out, int out_size) {
    const float* x  = (const float*)d_in[0];   // [B,3,1]
    const float* nb = (const float*)d_in[1];   // [B,3,64]
    const float* Ws = (const float*)d_in[2];   // [3,3]
    const float* bs = (const float*)d_in[3];   // [3]
    const float* Wc = (const float*)d_in[4];   // [3,3,2]
    const float* bc = (const float*)d_in[5];   // [3]
    float* out = (float*)d_out;                // [B,3,1]

    const int B = in_sizes[0] / 3;
    const int threads = 256;                   // 32 nodes per block
    const long long total = (long long)B * 8;
    const int blocks = (int)((total + threads - 1) / threads);

    gnn_kernel<<<blocks, threads>>>(x, nb, Ws, bs, Wc, bc, out, B);
}

// round 17
// speedup vs baseline: 1.1288x; 1.0176x over previous
#include <cuda_runtime.h>

// GNN_70145405878616 — FINAL (best measured 111.2us ≈ 7.1 TB/s effective):
// 8 lanes/node, coalesced 128B streaming loads (__ldcs), 3-lane epilogue,
// smem-staged sector-exact float4 output stores, 256-thread blocks.
// out[b,o] = tanh(tanh( bc[o] + sum_c Wc[o,c,0]*h[b,c] + Wc[o,c,1]*p[b,c] ))
//   h[b,c] = tanh( bs[c] + sum_j Ws[c,j]*x[b,j] ),  p[b,c] = mean_k nb[b,c,k]

__device__ __forceinline__ float htanh(float x) {
    float y;
    asm("tanh.approx.f32 %0, %1;" : "=f"(y) : "f"(x));
    return y;
}

__global__ __launch_bounds__(256) void gnn_kernel(
        const float* __restrict__ x,
        const float* __restrict__ nb,
        const float* __restrict__ Ws,
        const float* __restrict__ bs,
        const float* __restrict__ Wc,
        const float* __restrict__ bc,
        float* __restrict__ out,
        int B) {
    __shared__ float so[96];               // 32 nodes * 3 channels = 384 B

    const int gtid  = blockIdx.x * blockDim.x + threadIdx.x;
    const int node  = gtid >> 3;           // 8 lanes per node
    const int lane  = gtid & 7;
    const int lnode = threadIdx.x >> 3;    // node index within block (0..31)
    const bool live = (node < B);

    float s0 = 0.f, s1 = 0.f, s2 = 0.f;
    float x0 = 0.f, x1 = 0.f, x2 = 0.f;

    if (live) {
        const float4* __restrict__ base =
            reinterpret_cast<const float4*>(nb) + (size_t)node * 48;

        // Channel c occupies float4s [c*16, c*16+16). Lane l takes l and l+8.
        // Evict-first: stream is read exactly once.
        float4 a0 = __ldcs(base + lane),      b0 = __ldcs(base + lane + 8);
        float4 a1 = __ldcs(base + lane + 16), b1 = __ldcs(base + lane + 24);
        float4 a2 = __ldcs(base + lane + 32), b2 = __ldcs(base + lane + 40);

        if (lane < 3) {
            const float* __restrict__ xp = x + (size_t)node * 3;
            x0 = __ldg(xp + 0); x1 = __ldg(xp + 1); x2 = __ldg(xp + 2);
        }

        s0 = ((a0.x + b0.x) + (a0.y + b0.y)) + ((a0.z + b0.z) + (a0.w + b0.w));
        s1 = ((a1.x + b1.x) + (a1.y + b1.y)) + ((a1.z + b1.z) + (a1.w + b1.w));
        s2 = ((a2.x + b2.x) + (a2.y + b2.y)) + ((a2.z + b2.z) + (a2.w + b2.w));
    }

    // Reduce across the 8-lane group; all lanes end with the full sums.
    const unsigned gm = 0xFFu << (threadIdx.x & 24);
    #pragma unroll
    for (int off = 4; off > 0; off >>= 1) {
        s0 += __shfl_xor_sync(gm, s0, off);
        s1 += __shfl_xor_sync(gm, s1, off);
        s2 += __shfl_xor_sync(gm, s2, off);
    }

    if (live && lane < 3) {
        const int o = lane;
        const float inv = 1.0f / 64.0f;
        const float p[3] = { s0 * inv, s1 * inv, s2 * inv };

        float h[3];
        #pragma unroll
        for (int c = 0; c < 3; ++c) {
            h[c] = htanh(fmaf(__ldg(Ws + c * 3 + 0), x0,
                         fmaf(__ldg(Ws + c * 3 + 1), x1,
                         fmaf(__ldg(Ws + c * 3 + 2), x2, __ldg(bs + c)))));
        }

        float z = __ldg(bc + o);
        #pragma unroll
        for (int c = 0; c < 3; ++c) {
            z = fmaf(__ldg(Wc + o * 6 + c * 2 + 0), h[c], z);
            z = fmaf(__ldg(Wc + o * 6 + c * 2 + 1), p[c], z);
        }
        so[lnode * 3 + o] = htanh(htanh(z));
    }

    __syncthreads();

    // Sector-exact output: this block owns out[first*3 .. first*3+96),
    // a 384B 128-aligned span -> 24 float4 stores (full blocks only).
    const int first = blockIdx.x << 5;               // first node of block
    const int nodes_here = min(32, B - first);
    if (nodes_here == 32) {
        if (threadIdx.x < 24) {
            float4* __restrict__ o4 =
                reinterpret_cast<float4*>(out + (size_t)first * 3);
            const float4* s4 = reinterpret_cast<const float4*>(so);
            __stcs(o4 + threadIdx.x, s4[threadIdx.x]);
        }
    } else if (nodes_here > 0) {
        for (int i = threadIdx.x; i < nodes_here * 3; i += blockDim.x)
            out[(size_t)first * 3 + i] = so[i];
    }
}

extern "C" void kernel_launch(void* const* d_in, const int* in_sizes, int n_in,
                              void* d_out, int out_size) {
    const float* x  = (const float*)d_in[0];   // [B,3,1]
    const float* nb = (const float*)d_in[1];   // [B,3,64]
    const float* Ws = (const float*)d_in[2];   // [3,3]
    const float* bs = (const float*)d_in[3];   // [3]
    const float* Wc = (const float*)d_in[4];   // [3,3,2]
    const float* bc = (const float*)d_in[5];   // [3]
    float* out = (float*)d_out;                // [B,3,1]

    const int B = in_sizes[0] / 3;
    const int threads = 256;                   // 32 nodes per block
    const long long total = (long long)B * 8;
    const int blocks = (int)((total + threads - 1) / threads);

    gnn_kernel<<<blocks, threads>>>(x, nb, Ws, bs, Wc, bc, out, B);
}